// round 3
// baseline (speedup 1.0000x reference)
#include <cuda_runtime.h>
#include <math.h>

typedef unsigned long long ull;

// Problem dims
#define T_ 512
#define B_ 64
#define F_ 256
#define H_ 1024
#define C_ 257

// ---------------------------------------------------------------------------
// Scratch (device globals; no allocation allowed)
// ---------------------------------------------------------------------------
__device__ float g_gates[(size_t)T_ * H_ * B_ * 4]; // [t][j][b][g]  (g = f,i,o,c)
__device__ float g_hT[(size_t)T_ * H_ * B_];        // [t][j][b]
__device__ float g_Wpk[(size_t)128 * H_ * 32];      // [jt][k(1024)][r(32)] r = jj*4+g
__device__ float g_WXpk[(size_t)128 * F_ * 32];     // [jt][k(256)][r(32)]
__device__ float g_FCpk[(size_t)9 * H_ * 32];       // [ct][k(1024)][cc(32)] zero-pad c>=257
__device__ float g_xT[(size_t)T_ * F_ * B_];        // [t][k][b]
__device__ int   g_flag[(size_t)T_ * 128];          // [t][jt] h-ready flags

// ---------------------------------------------------------------------------
// f32x2 packed-FMA helpers (Blackwell FFMA2 — only reachable via PTX)
// ---------------------------------------------------------------------------
__device__ __forceinline__ ull pkdup(float v) {
    ull r;
    asm("mov.b64 %0, {%1, %1};" : "=l"(r) : "r"(__float_as_uint(v)));
    return r;
}
__device__ __forceinline__ void fma2(ull& d, ull a, ull b) {
    asm("fma.rn.f32x2 %0, %1, %2, %0;" : "+l"(d) : "l"(a), "l"(b));
}
__device__ __forceinline__ float lo2(ull v) {
    return __uint_as_float((unsigned)(v & 0xffffffffull));
}
__device__ __forceinline__ float hi2(ull v) {
    return __uint_as_float((unsigned)(v >> 32));
}

__device__ __forceinline__ float sigf(float x) {
    return 1.0f / (1.0f + expf(-x));
}
__device__ __forceinline__ float tanh_acc(float x) {
    float ax = fabsf(x);
    float e = expf(-2.0f * ax);
    float r = (1.0f - e) / (1.0f + e);
    return copysignf(r, x);
}

// ---------------------------------------------------------------------------
// Repack kernels
// ---------------------------------------------------------------------------
__global__ void prep_wh(const float* __restrict__ wf, const float* __restrict__ wi,
                        const float* __restrict__ wo, const float* __restrict__ wc) {
    const int total = 128 * H_ * 32;
    for (int idx = blockIdx.x * blockDim.x + threadIdx.x; idx < total;
         idx += gridDim.x * blockDim.x) {
        int r = idx & 31;
        int k = (idx >> 5) & (H_ - 1);
        int jt = idx >> 15;
        int g = r & 3;
        int jj = r >> 2;
        int j = jt * 8 + jj;
        const float* w = (g == 0) ? wf : (g == 1) ? wi : (g == 2) ? wo : wc;
        g_Wpk[idx] = w[(size_t)j * H_ + k];
    }
}

__global__ void prep_wx(const float* __restrict__ wf, const float* __restrict__ wi,
                        const float* __restrict__ wo, const float* __restrict__ wc) {
    const int total = 128 * F_ * 32;
    for (int idx = blockIdx.x * blockDim.x + threadIdx.x; idx < total;
         idx += gridDim.x * blockDim.x) {
        int r = idx & 31;
        int k = (idx >> 5) & (F_ - 1);
        int jt = idx >> 13;
        int g = r & 3;
        int jj = r >> 2;
        int j = jt * 8 + jj;
        const float* w = (g == 0) ? wf : (g == 1) ? wi : (g == 2) ? wo : wc;
        g_WXpk[idx] = w[(size_t)j * F_ + k];
    }
}

__global__ void prep_fc(const float* __restrict__ fco_w) {
    const int total = 9 * H_ * 32;
    for (int idx = blockIdx.x * blockDim.x + threadIdx.x; idx < total;
         idx += gridDim.x * blockDim.x) {
        int cc = idx & 31;
        int k = (idx >> 5) & (H_ - 1);
        int ct = idx >> 15;
        int c = ct * 32 + cc;
        g_FCpk[idx] = (c < C_) ? fco_w[(size_t)c * H_ + k] : 0.0f;
    }
}

__global__ void prep_xt(const float* __restrict__ x) {
    const int total = T_ * F_ * B_;
    for (int idx = blockIdx.x * blockDim.x + threadIdx.x; idx < total;
         idx += gridDim.x * blockDim.x) {
        int b = idx & (B_ - 1);
        int k = (idx >> 6) & (F_ - 1);
        int t = idx >> 14;
        g_xT[idx] = x[((size_t)t * B_ + b) * F_ + k];
    }
}

__global__ void prep_zero() {
    int i = blockIdx.x * blockDim.x + threadIdx.x;
    if (i < T_ * 128) g_flag[i] = 0;
}

// ---------------------------------------------------------------------------
// GEMM core for gates/out kernels (unchanged from R1, known-good).
// CTA tile 32 rows x 64 cols, 128 threads, K chunks of 32, double-buffered.
// ---------------------------------------------------------------------------
template <int NK>
__device__ __forceinline__ void gemm_core(const float4* __restrict__ Ag,
                                          const float4* __restrict__ Bg,
                                          float4 (*sA)[256], float4 (*sB)[512],
                                          ull (&acc)[4][2]) {
    const int tid = threadIdx.x;
    const int tn = tid >> 4;
    const int tb = tid & 15;

    float4 ra0, ra1, rb0, rb1, rb2, rb3;
    ra0 = Ag[tid];       ra1 = Ag[tid + 128];
    rb0 = Bg[tid];       rb1 = Bg[tid + 128];
    rb2 = Bg[tid + 256]; rb3 = Bg[tid + 384];
    sA[0][tid] = ra0;       sA[0][tid + 128] = ra1;
    sB[0][tid] = rb0;       sB[0][tid + 128] = rb1;
    sB[0][tid + 256] = rb2; sB[0][tid + 384] = rb3;
    __syncthreads();

#pragma unroll 1
    for (int ch = 0; ch < NK; ++ch) {
        const int cur = ch & 1;
        const int nxt = cur ^ 1;
        if (ch + 1 < NK) {
            const float4* An = Ag + (size_t)(ch + 1) * 256;
            const float4* Bn = Bg + (size_t)(ch + 1) * 512;
            ra0 = An[tid];       ra1 = An[tid + 128];
            rb0 = Bn[tid];       rb1 = Bn[tid + 128];
            rb2 = Bn[tid + 256]; rb3 = Bn[tid + 384];
        }
        const float4* A = sA[cur];
        const float4* Bv = sB[cur];
#pragma unroll
        for (int kk = 0; kk < 32; ++kk) {
            float4 a = A[kk * 8 + tn];
            const ull* bp = reinterpret_cast<const ull*>(&Bv[kk * 16 + tb]);
            ull b0 = bp[0];
            ull b1 = bp[1];
            ull a0 = pkdup(a.x);
            ull a1 = pkdup(a.y);
            ull a2 = pkdup(a.z);
            ull a3 = pkdup(a.w);
            fma2(acc[0][0], a0, b0); fma2(acc[0][1], a0, b1);
            fma2(acc[1][0], a1, b0); fma2(acc[1][1], a1, b1);
            fma2(acc[2][0], a2, b0); fma2(acc[2][1], a2, b1);
            fma2(acc[3][0], a3, b0); fma2(acc[3][1], a3, b1);
        }
        __syncthreads();
        if (ch + 1 < NK) {
            sA[nxt][tid] = ra0;       sA[nxt][tid + 128] = ra1;
            sB[nxt][tid] = rb0;       sB[nxt][tid + 128] = rb1;
            sB[nxt][tid + 256] = rb2; sB[nxt][tid + 384] = rb3;
            __syncthreads();
        }
    }
}

__device__ __forceinline__ void unpack_acc(const ull (&acc)[4][2], float (&z)[4][4]) {
#pragma unroll
    for (int r = 0; r < 4; ++r) {
        z[r][0] = lo2(acc[r][0]);
        z[r][1] = hi2(acc[r][0]);
        z[r][2] = lo2(acc[r][1]);
        z[r][3] = hi2(acc[r][1]);
    }
}

// ---------------------------------------------------------------------------
// Input-projection GEMM: gates[t][j][b][4]
// ---------------------------------------------------------------------------
__global__ void k_gates(const float* __restrict__ bf, const float* __restrict__ bi,
                        const float* __restrict__ bo, const float* __restrict__ bc) {
    const int jt = blockIdx.x;
    const int t = blockIdx.y;
    __shared__ float4 sA[2][256];
    __shared__ float4 sB[2][512];
    ull acc[4][2] = {};

    const float4* Ag = reinterpret_cast<const float4*>(g_WXpk) + (size_t)jt * F_ * 8;
    const float4* Bg = reinterpret_cast<const float4*>(g_xT) + (size_t)t * F_ * 16;
    gemm_core<F_ / 32>(Ag, Bg, sA, sB, acc);

    const int tn = threadIdx.x >> 4;
    const int tb = threadIdx.x & 15;
    const int j = jt * 8 + tn;
    float z[4][4];
    unpack_acc(acc, z);
    const float b0 = bf[j], b1 = bi[j], b2 = bo[j], b3 = bc[j];
    float4* G = reinterpret_cast<float4*>(g_gates) + ((size_t)t * H_ + j) * 64 + tb * 4;
#pragma unroll
    for (int bb = 0; bb < 4; ++bb) {
        G[bb] = make_float4(z[0][bb] + b0, z[1][bb] + b1, z[2][bb] + b2, z[3][bb] + b3);
    }
}

// ---------------------------------------------------------------------------
// Flag wait: chunk kc of step t needs h rows kc*32..+31 => CTAs kc*4..kc*4+3.
// ---------------------------------------------------------------------------
__device__ __forceinline__ void waitf(int t, int kc) {
    const int* f = g_flag + t * 128 + kc * 4;
    while (true) {
        int a0, a1, a2, a3;
        asm volatile(
            "ld.volatile.global.s32 %0, [%4];\n\t"
            "ld.volatile.global.s32 %1, [%4+4];\n\t"
            "ld.volatile.global.s32 %2, [%4+8];\n\t"
            "ld.volatile.global.s32 %3, [%4+12];"
            : "=r"(a0), "=r"(a1), "=r"(a2), "=r"(a3)
            : "l"(f));
        if (a0 & a1 & a2 & a3) break;
        __nanosleep(40);
    }
}

// ---------------------------------------------------------------------------
// Persistent recurrence kernel. 128 CTAs x 256 threads. CTA jt owns
// j = jt*8..+7 (rows r = jj*4+g, 32 rows). Weights resident in SMEM (128 KB).
// Warp tile 16 rows x 16 cols: wr=wid>>2 (row half), wc=wid&3 (col quarter).
// Thread: 4 rows (one jj, gates f,i,o,c) x 2 cols. acc packed along gate
// pairs (f,i)/(o,c) so A SMEM loads give the f32x2 operand directly.
// ---------------------------------------------------------------------------
__global__ void __launch_bounds__(256, 1) k_rec() {
    extern __shared__ float smem[];
    float* sW = smem;              // [1024][32]
    float* sB = smem + H_ * 32;    // 2 x [32][64]

    const int tid = threadIdx.x;
    const int jt = blockIdx.x;

    // Load this CTA's weight slice once (128 KB).
    {
        const float4* Wg =
            reinterpret_cast<const float4*>(g_Wpk + (size_t)jt * H_ * 32);
        float4* sW4 = reinterpret_cast<float4*>(sW);
#pragma unroll
        for (int i = 0; i < 32; ++i) sW4[tid + i * 256] = Wg[tid + i * 256];
    }
    __syncthreads();

    const int wid = tid >> 5, lane = tid & 31;
    const int wr = wid >> 2, wc = wid & 3;
    const int lr = lane >> 3, cb = lane & 7;
    const int rr = wr * 16 + lr * 4;  // row base within 32-row tile (= jj*4)
    const int j = jt * 8 + (rr >> 2);
    const int b0 = wc * 16 + cb * 2;

    float c0 = 0.f, c1 = 0.f;
    const float4* hp4base = reinterpret_cast<const float4*>(g_hT);
    float4* sB4 = reinterpret_cast<float4*>(sB);

#pragma unroll 1
    for (int t = 0; t < T_; ++t) {
        ull acc00 = 0, acc01 = 0, acc10 = 0, acc11 = 0;
        if (t > 0) {
            const float4* hp4 = hp4base + (size_t)(t - 1) * 16384;
            // stage chunk 0
            waitf(t - 1, 0);
            {
                float4 p0 = hp4[tid], p1 = hp4[tid + 256];
                sB4[tid] = p0;
                sB4[tid + 256] = p1;
            }
            __syncthreads();
#pragma unroll 1
            for (int kc = 0; kc < 32; ++kc) {
                const float* cur = sB + (kc & 1) * 2048;
                float4 q0, q1;
                if (kc < 31) {
                    waitf(t - 1, kc + 1);
                    q0 = hp4[(kc + 1) * 512 + tid];
                    q1 = hp4[(kc + 1) * 512 + tid + 256];
                }
                const float* Wk = sW + (kc * 32) * 32;
#pragma unroll
                for (int kk = 0; kk < 32; ++kk) {
                    ulonglong2 av =
                        *reinterpret_cast<const ulonglong2*>(Wk + kk * 32 + rr);
                    float2 bv = *reinterpret_cast<const float2*>(cur + kk * 64 + b0);
                    ull bd0 = pkdup(bv.x);
                    ull bd1 = pkdup(bv.y);
                    fma2(acc00, av.x, bd0);
                    fma2(acc10, av.y, bd0);
                    fma2(acc01, av.x, bd1);
                    fma2(acc11, av.y, bd1);
                }
                __syncthreads();
                if (kc < 31) {
                    float4* nb = reinterpret_cast<float4*>(sB + ((kc + 1) & 1) * 2048);
                    nb[tid] = q0;
                    nb[tid + 256] = q1;
                    __syncthreads();
                }
            }
        }

        // Epilogue: add input gates, LSTM cell, write h, post flag.
        const float4* G4 =
            reinterpret_cast<const float4*>(g_gates) + ((size_t)t * H_ + j) * 64 + b0;
        float4 gx0 = G4[0];
        float4 gx1 = G4[1];

        float zf0 = lo2(acc00) + gx0.x, zi0 = hi2(acc00) + gx0.y;
        float zo0 = lo2(acc10) + gx0.z, zc0 = hi2(acc10) + gx0.w;
        float zf1 = lo2(acc01) + gx1.x, zi1 = hi2(acc01) + gx1.y;
        float zo1 = lo2(acc11) + gx1.z, zc1 = hi2(acc11) + gx1.w;

        float ft0 = sigf(zf0), it0 = sigf(zi0), ot0 = sigf(zo0);
        c0 = it0 * tanh_acc(zc0) + ft0 * c0;
        float h0v = ot0 * tanh_acc(c0);
        float ft1 = sigf(zf1), it1 = sigf(zi1), ot1 = sigf(zo1);
        c1 = it1 * tanh_acc(zc1) + ft1 * c1;
        float h1v = ot1 * tanh_acc(c1);

        float2 hv = make_float2(h0v, h1v);
        *reinterpret_cast<float2*>(g_hT + (size_t)t * (H_ * B_) + j * B_ + b0) = hv;
        __threadfence();
        __syncthreads();
        if (tid == 0) {
            asm volatile("st.volatile.global.s32 [%0], %1;"
                         :: "l"(g_flag + t * 128 + jt), "r"(1)
                         : "memory");
        }
    }
}

// ---------------------------------------------------------------------------
// Output projection: out[t][b][c] = hT[t][:,b] . fco_w[c,:] + fco_b[c]
// ---------------------------------------------------------------------------
__global__ void k_out(const float* __restrict__ fco_b, float* __restrict__ out) {
    const int ct = blockIdx.x;
    const int t = blockIdx.y;
    __shared__ float4 sA[2][256];
    __shared__ float4 sB[2][512];
    ull acc[4][2] = {};

    const float4* Ag = reinterpret_cast<const float4*>(g_FCpk) + (size_t)ct * H_ * 8;
    const float4* Bg = reinterpret_cast<const float4*>(g_hT) + (size_t)t * H_ * 16;
    gemm_core<H_ / 32>(Ag, Bg, sA, sB, acc);

    const int tn = threadIdx.x >> 4;
    const int tb = threadIdx.x & 15;
    const int c0 = ct * 32 + tn * 4;

    float z[4][4];
    unpack_acc(acc, z);

#pragma unroll
    for (int bb = 0; bb < 4; ++bb) {
        const int b = tb * 4 + bb;
        float* o = out + ((size_t)t * B_ + b) * C_;
#pragma unroll
        for (int ci = 0; ci < 4; ++ci) {
            const int c = c0 + ci;
            if (c < C_) o[c] = z[ci][bb] + fco_b[c];
        }
    }
}

// ---------------------------------------------------------------------------
// Launch
// ---------------------------------------------------------------------------
extern "C" void kernel_launch(void* const* d_in, const int* in_sizes, int n_in,
                              void* d_out, int out_size) {
    const float* x     = (const float*)d_in[0];
    const float* wfx_w = (const float*)d_in[1];
    const float* wfx_b = (const float*)d_in[2];
    const float* wix_w = (const float*)d_in[3];
    const float* wix_b = (const float*)d_in[4];
    const float* wox_w = (const float*)d_in[5];
    const float* wox_b = (const float*)d_in[6];
    const float* wcx_w = (const float*)d_in[7];
    const float* wcx_b = (const float*)d_in[8];
    const float* wfh_w = (const float*)d_in[9];
    const float* wih_w = (const float*)d_in[10];
    const float* woh_w = (const float*)d_in[11];
    const float* wch_w = (const float*)d_in[12];
    const float* fco_w = (const float*)d_in[13];
    const float* fco_b = (const float*)d_in[14];
    float* out = (float*)d_out;

    (void)in_sizes; (void)n_in; (void)out_size;

    const int rec_smem = (H_ * 32 + 2 * 32 * B_) * (int)sizeof(float); // 147456
    cudaFuncSetAttribute(k_rec, cudaFuncAttributeMaxDynamicSharedMemorySize,
                         rec_smem);

    prep_wh<<<4096, 256>>>(wfh_w, wih_w, woh_w, wch_w);
    prep_wx<<<2048, 256>>>(wfx_w, wix_w, wox_w, wcx_w);
    prep_fc<<<576, 256>>>(fco_w);
    prep_xt<<<4096, 256>>>(x);
    prep_zero<<<256, 256>>>();

    k_gates<<<dim3(128, 512), 128>>>(wfx_b, wix_b, wox_b, wcx_b);

    k_rec<<<128, 256, rec_smem>>>();

    k_out<<<dim3(9, 512), 128>>>(fco_b, out);
}

// round 5
// speedup vs baseline: 1.3722x; 1.3722x over previous
#include <cuda_runtime.h>
#include <math.h>

typedef unsigned long long ull;

// Problem dims
#define T_ 512
#define B_ 64
#define F_ 256
#define H_ 1024
#define C_ 257

// ---------------------------------------------------------------------------
// Scratch (device globals; no allocation allowed)
// ---------------------------------------------------------------------------
__device__ float g_gates[(size_t)T_ * H_ * B_ * 4]; // [t][j][b][g]  (g = f,i,o,c)
__device__ float g_hT[(size_t)T_ * H_ * B_];        // [t][j][b]           (k_out)
__device__ float g_hT2[(size_t)T_ * H_ * B_];       // [t][j>>1][b][2]     (k_rec)
__device__ float g_Wpk[(size_t)128 * H_ * 32];      // [jt][k(1024)][r(32)] r=jj*4+g
__device__ float g_WXpk[(size_t)128 * F_ * 32];     // [jt][k(256)][r(32)]
__device__ float g_FCpk[(size_t)9 * H_ * 32];       // [ct][k(1024)][cc] pad c>=257
__device__ float g_xT[(size_t)T_ * F_ * B_];        // [t][k][b]
__device__ int   g_flag[(size_t)T_ * 128];          // [t][jt] h-ready flags

// ---------------------------------------------------------------------------
// f32x2 packed-FMA helpers (Blackwell FFMA2 — only reachable via PTX)
// ---------------------------------------------------------------------------
__device__ __forceinline__ ull pkdup(float v) {
    ull r;
    asm("mov.b64 %0, {%1, %1};" : "=l"(r) : "r"(__float_as_uint(v)));
    return r;
}
__device__ __forceinline__ void fma2(ull& d, ull a, ull b) {
    asm("fma.rn.f32x2 %0, %1, %2, %0;" : "+l"(d) : "l"(a), "l"(b));
}
__device__ __forceinline__ float lo2(ull v) {
    return __uint_as_float((unsigned)(v & 0xffffffffull));
}
__device__ __forceinline__ float hi2(ull v) {
    return __uint_as_float((unsigned)(v >> 32));
}

__device__ __forceinline__ float sigf(float x) {
    return 1.0f / (1.0f + expf(-x));
}
__device__ __forceinline__ float tanh_acc(float x) {
    float ax = fabsf(x);
    float e = expf(-2.0f * ax);
    float r = (1.0f - e) / (1.0f + e);
    return copysignf(r, x);
}

// ---------------------------------------------------------------------------
// Repack kernels
// ---------------------------------------------------------------------------
__global__ void prep_wh(const float* __restrict__ wf, const float* __restrict__ wi,
                        const float* __restrict__ wo, const float* __restrict__ wc) {
    const int total = 128 * H_ * 32;
    for (int idx = blockIdx.x * blockDim.x + threadIdx.x; idx < total;
         idx += gridDim.x * blockDim.x) {
        int r = idx & 31;
        int k = (idx >> 5) & (H_ - 1);
        int jt = idx >> 15;
        int g = r & 3;
        int jj = r >> 2;
        int j = jt * 8 + jj;
        const float* w = (g == 0) ? wf : (g == 1) ? wi : (g == 2) ? wo : wc;
        g_Wpk[idx] = w[(size_t)j * H_ + k];
    }
}

__global__ void prep_wx(const float* __restrict__ wf, const float* __restrict__ wi,
                        const float* __restrict__ wo, const float* __restrict__ wc) {
    const int total = 128 * F_ * 32;
    for (int idx = blockIdx.x * blockDim.x + threadIdx.x; idx < total;
         idx += gridDim.x * blockDim.x) {
        int r = idx & 31;
        int k = (idx >> 5) & (F_ - 1);
        int jt = idx >> 13;
        int g = r & 3;
        int jj = r >> 2;
        int j = jt * 8 + jj;
        const float* w = (g == 0) ? wf : (g == 1) ? wi : (g == 2) ? wo : wc;
        g_WXpk[idx] = w[(size_t)j * F_ + k];
    }
}

__global__ void prep_fc(const float* __restrict__ fco_w) {
    const int total = 9 * H_ * 32;
    for (int idx = blockIdx.x * blockDim.x + threadIdx.x; idx < total;
         idx += gridDim.x * blockDim.x) {
        int cc = idx & 31;
        int k = (idx >> 5) & (H_ - 1);
        int ct = idx >> 15;
        int c = ct * 32 + cc;
        g_FCpk[idx] = (c < C_) ? fco_w[(size_t)c * H_ + k] : 0.0f;
    }
}

__global__ void prep_xt(const float* __restrict__ x) {
    const int total = T_ * F_ * B_;
    for (int idx = blockIdx.x * blockDim.x + threadIdx.x; idx < total;
         idx += gridDim.x * blockDim.x) {
        int b = idx & (B_ - 1);
        int k = (idx >> 6) & (F_ - 1);
        int t = idx >> 14;
        g_xT[idx] = x[((size_t)t * B_ + b) * F_ + k];
    }
}

__global__ void prep_zero() {
    int i = blockIdx.x * blockDim.x + threadIdx.x;
    if (i < T_ * 128) g_flag[i] = 0;
}

// ---------------------------------------------------------------------------
// GEMM core for gates/out kernels (known-good from R1).
// ---------------------------------------------------------------------------
template <int NK>
__device__ __forceinline__ void gemm_core(const float4* __restrict__ Ag,
                                          const float4* __restrict__ Bg,
                                          float4 (*sA)[256], float4 (*sB)[512],
                                          ull (&acc)[4][2]) {
    const int tid = threadIdx.x;
    const int tn = tid >> 4;
    const int tb = tid & 15;

    float4 ra0, ra1, rb0, rb1, rb2, rb3;
    ra0 = Ag[tid];       ra1 = Ag[tid + 128];
    rb0 = Bg[tid];       rb1 = Bg[tid + 128];
    rb2 = Bg[tid + 256]; rb3 = Bg[tid + 384];
    sA[0][tid] = ra0;       sA[0][tid + 128] = ra1;
    sB[0][tid] = rb0;       sB[0][tid + 128] = rb1;
    sB[0][tid + 256] = rb2; sB[0][tid + 384] = rb3;
    __syncthreads();

#pragma unroll 1
    for (int ch = 0; ch < NK; ++ch) {
        const int cur = ch & 1;
        const int nxt = cur ^ 1;
        if (ch + 1 < NK) {
            const float4* An = Ag + (size_t)(ch + 1) * 256;
            const float4* Bn = Bg + (size_t)(ch + 1) * 512;
            ra0 = An[tid];       ra1 = An[tid + 128];
            rb0 = Bn[tid];       rb1 = Bn[tid + 128];
            rb2 = Bn[tid + 256]; rb3 = Bn[tid + 384];
        }
        const float4* A = sA[cur];
        const float4* Bv = sB[cur];
#pragma unroll
        for (int kk = 0; kk < 32; ++kk) {
            float4 a = A[kk * 8 + tn];
            const ull* bp = reinterpret_cast<const ull*>(&Bv[kk * 16 + tb]);
            ull b0 = bp[0];
            ull b1 = bp[1];
            ull a0 = pkdup(a.x);
            ull a1 = pkdup(a.y);
            ull a2 = pkdup(a.z);
            ull a3 = pkdup(a.w);
            fma2(acc[0][0], a0, b0); fma2(acc[0][1], a0, b1);
            fma2(acc[1][0], a1, b0); fma2(acc[1][1], a1, b1);
            fma2(acc[2][0], a2, b0); fma2(acc[2][1], a2, b1);
            fma2(acc[3][0], a3, b0); fma2(acc[3][1], a3, b1);
        }
        __syncthreads();
        if (ch + 1 < NK) {
            sA[nxt][tid] = ra0;       sA[nxt][tid + 128] = ra1;
            sB[nxt][tid] = rb0;       sB[nxt][tid + 128] = rb1;
            sB[nxt][tid + 256] = rb2; sB[nxt][tid + 384] = rb3;
            __syncthreads();
        }
    }
}

__device__ __forceinline__ void unpack_acc(const ull (&acc)[4][2], float (&z)[4][4]) {
#pragma unroll
    for (int r = 0; r < 4; ++r) {
        z[r][0] = lo2(acc[r][0]);
        z[r][1] = hi2(acc[r][0]);
        z[r][2] = lo2(acc[r][1]);
        z[r][3] = hi2(acc[r][1]);
    }
}

// ---------------------------------------------------------------------------
// Input-projection GEMM: gates[t][j][b][4]
// ---------------------------------------------------------------------------
__global__ void k_gates(const float* __restrict__ bf, const float* __restrict__ bi,
                        const float* __restrict__ bo, const float* __restrict__ bc) {
    const int jt = blockIdx.x;
    const int t = blockIdx.y;
    __shared__ float4 sA[2][256];
    __shared__ float4 sB[2][512];
    ull acc[4][2] = {};

    const float4* Ag = reinterpret_cast<const float4*>(g_WXpk) + (size_t)jt * F_ * 8;
    const float4* Bg = reinterpret_cast<const float4*>(g_xT) + (size_t)t * F_ * 16;
    gemm_core<F_ / 32>(Ag, Bg, sA, sB, acc);

    const int tn = threadIdx.x >> 4;
    const int tb = threadIdx.x & 15;
    const int j = jt * 8 + tn;
    float z[4][4];
    unpack_acc(acc, z);
    const float b0 = bf[j], b1 = bi[j], b2 = bo[j], b3 = bc[j];
    float4* G = reinterpret_cast<float4*>(g_gates) + ((size_t)t * H_ + j) * 64 + tb * 4;
#pragma unroll
    for (int bb = 0; bb < 4; ++bb) {
        G[bb] = make_float4(z[0][bb] + b0, z[1][bb] + b1, z[2][bb] + b2, z[3][bb] + b3);
    }
}

// ---------------------------------------------------------------------------
// Persistent recurrence kernel. 128 CTAs x 256 threads. CTA jt owns rows
// j = jt*8..+7 (32 gate-rows). Weights resident in SMEM (128 KB) all 512 steps.
// B (h of t-1) staged per 64-k chunk, single-sync double buffer, kk-pair
// interleaved so one LDS.128 feeds 2 k-steps of the B operand.
// Release protocol (R2-proven): per-thread __threadfence -> bar -> tid0 flag.
// ---------------------------------------------------------------------------
__global__ void __launch_bounds__(256, 1) k_rec() {
    extern __shared__ float smem[];
    float* sW = smem;              // [1024][32]  = 128 KB
    float* sB2 = smem + H_ * 32;   // 2 x [32 kk2][64 b][2] = 2 x 16 KB

    const int tid = threadIdx.x;
    const int jt = blockIdx.x;

    // Load this CTA's weight slice once (128 KB).
    {
        const float4* Wg =
            reinterpret_cast<const float4*>(g_Wpk + (size_t)jt * H_ * 32);
        float4* sW4 = reinterpret_cast<float4*>(sW);
#pragma unroll
        for (int i = 0; i < 32; ++i) sW4[tid + i * 256] = Wg[tid + i * 256];
    }
    __syncthreads();

    const int wid = tid >> 5, lane = tid & 31;
    const int wr = wid >> 2, wc = wid & 3;
    const int lr = lane >> 3, cb = lane & 7;
    const int rr = wr * 16 + lr * 4;  // row base within 32-row tile (= jj*4)
    const int j = jt * 8 + (rr >> 2);
    const int b0 = wc * 16 + cb * 2;

    float c0 = 0.f, c1 = 0.f;
    float4* sB4 = reinterpret_cast<float4*>(sB2);

#pragma unroll 1
    for (int t = 0; t < T_; ++t) {
        // Prefetch this step's input-projection gates (independent of flags).
        const float4* G4 =
            reinterpret_cast<const float4*>(g_gates) + ((size_t)t * H_ + j) * 64 + b0;
        float4 gx0 = G4[0];
        float4 gx1 = G4[1];

        ull acc00 = 0, acc01 = 0, acc10 = 0, acc11 = 0;
        if (t > 0) {
            // One parallel wait for all 128 producer flags of step t-1.
            if (tid < 128) {
                const int* f = g_flag + (t - 1) * 128 + tid;
                int v;
                do {
                    asm volatile("ld.volatile.global.s32 %0, [%1];"
                                 : "=r"(v) : "l"(f));
                } while (!v);
            }
            __syncthreads();

            const float4* hp4 =
                reinterpret_cast<const float4*>(g_hT2) + (size_t)(t - 1) * 16384;

            // Stage chunk 0 (16 KB -> buffer 0).
            {
                float4 p0 = hp4[tid], p1 = hp4[tid + 256];
                float4 p2 = hp4[tid + 512], p3 = hp4[tid + 768];
                sB4[tid] = p0;        sB4[tid + 256] = p1;
                sB4[tid + 512] = p2;  sB4[tid + 768] = p3;
            }
            __syncthreads();

#pragma unroll 1
            for (int kc = 0; kc < 16; ++kc) {
                float4 q0, q1, q2, q3;
                if (kc < 15) {
                    const float4* hn = hp4 + (size_t)(kc + 1) * 1024;
                    q0 = hn[tid];       q1 = hn[tid + 256];
                    q2 = hn[tid + 512]; q3 = hn[tid + 768];
                }
                const float* Wk = sW + (kc * 64) * 32;
                const float* Bc = sB2 + (kc & 1) * 4096;
#pragma unroll
                for (int kk2 = 0; kk2 < 32; ++kk2) {
                    ulonglong2 av0 =
                        *reinterpret_cast<const ulonglong2*>(Wk + (2 * kk2) * 32 + rr);
                    ulonglong2 av1 =
                        *reinterpret_cast<const ulonglong2*>(Wk + (2 * kk2 + 1) * 32 + rr);
                    float4 bq =
                        *reinterpret_cast<const float4*>(Bc + kk2 * 128 + b0 * 2);
                    ull b00 = pkdup(bq.x);  // kk even, col b0
                    ull b10 = pkdup(bq.y);  // kk odd,  col b0
                    ull b01 = pkdup(bq.z);  // kk even, col b0+1
                    ull b11 = pkdup(bq.w);  // kk odd,  col b0+1
                    fma2(acc00, av0.x, b00); fma2(acc10, av0.y, b00);
                    fma2(acc01, av0.x, b01); fma2(acc11, av0.y, b01);
                    fma2(acc00, av1.x, b10); fma2(acc10, av1.y, b10);
                    fma2(acc01, av1.x, b11); fma2(acc11, av1.y, b11);
                }
                if (kc < 15) {
                    float4* nb = reinterpret_cast<float4*>(sB2 + ((kc + 1) & 1) * 4096);
                    nb[tid] = q0;       nb[tid + 256] = q1;
                    nb[tid + 512] = q2; nb[tid + 768] = q3;
                    __syncthreads();
                }
            }
        }

        // Epilogue: add input gates, LSTM cell, write h (both layouts), flag.
        float zf0 = lo2(acc00) + gx0.x, zi0 = hi2(acc00) + gx0.y;
        float zo0 = lo2(acc10) + gx0.z, zc0 = hi2(acc10) + gx0.w;
        float zf1 = lo2(acc01) + gx1.x, zi1 = hi2(acc01) + gx1.y;
        float zo1 = lo2(acc11) + gx1.z, zc1 = hi2(acc11) + gx1.w;

        float ft0 = sigf(zf0), it0 = sigf(zi0), ot0 = sigf(zo0);
        c0 = it0 * tanh_acc(zc0) + ft0 * c0;
        float h0v = ot0 * tanh_acc(c0);
        float ft1 = sigf(zf1), it1 = sigf(zi1), ot1 = sigf(zo1);
        c1 = it1 * tanh_acc(zc1) + ft1 * c1;
        float h1v = ot1 * tanh_acc(c1);

        // Plain layout for k_out.
        *reinterpret_cast<float2*>(g_hT + (size_t)t * (H_ * B_) + j * B_ + b0) =
            make_float2(h0v, h1v);
        // kk-pair interleaved layout for k_rec's B loads.
        {
            float* p = g_hT2 + (((size_t)t * 512 + (j >> 1)) * 64 + b0) * 2 + (j & 1);
            p[0] = h0v;
            p[2] = h1v;
        }
        // R2-proven release: every thread fences its own stores, then bar,
        // then one thread publishes the flag.
        __threadfence();
        __syncthreads();
        if (tid == 0) {
            asm volatile("st.volatile.global.s32 [%0], %1;"
                         :: "l"(g_flag + t * 128 + jt), "r"(1)
                         : "memory");
        }
    }
}

// ---------------------------------------------------------------------------
// Output projection: out[t][b][c] = hT[t][:,b] . fco_w[c,:] + fco_b[c]
// ---------------------------------------------------------------------------
__global__ void k_out(const float* __restrict__ fco_b, float* __restrict__ out) {
    const int ct = blockIdx.x;
    const int t = blockIdx.y;
    __shared__ float4 sA[2][256];
    __shared__ float4 sB[2][512];
    ull acc[4][2] = {};

    const float4* Ag = reinterpret_cast<const float4*>(g_FCpk) + (size_t)ct * H_ * 8;
    const float4* Bg = reinterpret_cast<const float4*>(g_hT) + (size_t)t * H_ * 16;
    gemm_core<H_ / 32>(Ag, Bg, sA, sB, acc);

    const int tn = threadIdx.x >> 4;
    const int tb = threadIdx.x & 15;
    const int c0 = ct * 32 + tn * 4;

    float z[4][4];
    unpack_acc(acc, z);

#pragma unroll
    for (int bb = 0; bb < 4; ++bb) {
        const int b = tb * 4 + bb;
        float* o = out + ((size_t)t * B_ + b) * C_;
#pragma unroll
        for (int ci = 0; ci < 4; ++ci) {
            const int c = c0 + ci;
            if (c < C_) o[c] = z[ci][bb] + fco_b[c];
        }
    }
}

// ---------------------------------------------------------------------------
// Launch
// ---------------------------------------------------------------------------
extern "C" void kernel_launch(void* const* d_in, const int* in_sizes, int n_in,
                              void* d_out, int out_size) {
    const float* x     = (const float*)d_in[0];
    const float* wfx_w = (const float*)d_in[1];
    const float* wfx_b = (const float*)d_in[2];
    const float* wix_w = (const float*)d_in[3];
    const float* wix_b = (const float*)d_in[4];
    const float* wox_w = (const float*)d_in[5];
    const float* wox_b = (const float*)d_in[6];
    const float* wcx_w = (const float*)d_in[7];
    const float* wcx_b = (const float*)d_in[8];
    const float* wfh_w = (const float*)d_in[9];
    const float* wih_w = (const float*)d_in[10];
    const float* woh_w = (const float*)d_in[11];
    const float* wch_w = (const float*)d_in[12];
    const float* fco_w = (const float*)d_in[13];
    const float* fco_b = (const float*)d_in[14];
    float* out = (float*)d_out;

    (void)in_sizes; (void)n_in; (void)out_size;

    const int rec_smem = (H_ * 32 + 2 * 4096) * (int)sizeof(float); // 163840
    cudaFuncSetAttribute(k_rec, cudaFuncAttributeMaxDynamicSharedMemorySize,
                         rec_smem);

    prep_wh<<<4096, 256>>>(wfh_w, wih_w, woh_w, wch_w);
    prep_wx<<<2048, 256>>>(wfx_w, wix_w, wox_w, wcx_w);
    prep_fc<<<576, 256>>>(fco_w);
    prep_xt<<<4096, 256>>>(x);
    prep_zero<<<256, 256>>>();

    k_gates<<<dim3(128, 512), 128>>>(wfx_b, wix_b, wox_b, wcx_b);

    k_rec<<<128, 256, rec_smem>>>();

    k_out<<<dim3(9, 512), 128>>>(fco_b, out);
}

// round 6
// speedup vs baseline: 1.3860x; 1.0100x over previous
#include <cuda_runtime.h>
#include <math.h>

typedef unsigned long long ull;

// Problem dims
#define T_ 512
#define B_ 64
#define F_ 256
#define H_ 1024
#define C_ 257

// ---------------------------------------------------------------------------
// Scratch (device globals; no allocation allowed)
// ---------------------------------------------------------------------------
__device__ float g_gates[(size_t)T_ * H_ * B_ * 4]; // [t][j][b][g]  (g = f,i,o,c)
__device__ float g_hT[(size_t)T_ * H_ * B_];        // [t][j][b]           (k_out)
__device__ float g_hT2[(size_t)T_ * H_ * B_];       // [t][j>>1][b][2]     (k_rec)
__device__ float g_Wpk[(size_t)128 * H_ * 32];      // [jt][k(1024)][r(32)] r=jj*4+g
__device__ float g_WXpk[(size_t)128 * F_ * 32];     // [jt][k(256)][r(32)]
__device__ float g_FCpk[(size_t)9 * H_ * 32];       // [ct][k(1024)][cc] pad c>=257
__device__ float g_xT[(size_t)T_ * F_ * B_];        // [t][k][b]
__device__ int   g_flag[(size_t)T_ * 128];          // [t][jt] h-ready flags

// ---------------------------------------------------------------------------
// f32x2 packed-FMA helpers (Blackwell FFMA2 — only reachable via PTX)
// ---------------------------------------------------------------------------
__device__ __forceinline__ ull pkdup(float v) {
    ull r;
    asm("mov.b64 %0, {%1, %1};" : "=l"(r) : "r"(__float_as_uint(v)));
    return r;
}
__device__ __forceinline__ void fma2(ull& d, ull a, ull b) {
    asm("fma.rn.f32x2 %0, %1, %2, %0;" : "+l"(d) : "l"(a), "l"(b));
}
__device__ __forceinline__ float lo2(ull v) {
    return __uint_as_float((unsigned)(v & 0xffffffffull));
}
__device__ __forceinline__ float hi2(ull v) {
    return __uint_as_float((unsigned)(v >> 32));
}

__device__ __forceinline__ float sigf(float x) {
    return 1.0f / (1.0f + expf(-x));
}
__device__ __forceinline__ float tanh_acc(float x) {
    float ax = fabsf(x);
    float e = expf(-2.0f * ax);
    float r = (1.0f - e) / (1.0f + e);
    return copysignf(r, x);
}

// ---------------------------------------------------------------------------
// Repack kernels
// ---------------------------------------------------------------------------
__global__ void prep_wh(const float* __restrict__ wf, const float* __restrict__ wi,
                        const float* __restrict__ wo, const float* __restrict__ wc) {
    const int total = 128 * H_ * 32;
    for (int idx = blockIdx.x * blockDim.x + threadIdx.x; idx < total;
         idx += gridDim.x * blockDim.x) {
        int r = idx & 31;
        int k = (idx >> 5) & (H_ - 1);
        int jt = idx >> 15;
        int g = r & 3;
        int jj = r >> 2;
        int j = jt * 8 + jj;
        const float* w = (g == 0) ? wf : (g == 1) ? wi : (g == 2) ? wo : wc;
        g_Wpk[idx] = w[(size_t)j * H_ + k];
    }
}

__global__ void prep_wx(const float* __restrict__ wf, const float* __restrict__ wi,
                        const float* __restrict__ wo, const float* __restrict__ wc) {
    const int total = 128 * F_ * 32;
    for (int idx = blockIdx.x * blockDim.x + threadIdx.x; idx < total;
         idx += gridDim.x * blockDim.x) {
        int r = idx & 31;
        int k = (idx >> 5) & (F_ - 1);
        int jt = idx >> 13;
        int g = r & 3;
        int jj = r >> 2;
        int j = jt * 8 + jj;
        const float* w = (g == 0) ? wf : (g == 1) ? wi : (g == 2) ? wo : wc;
        g_WXpk[idx] = w[(size_t)j * F_ + k];
    }
}

__global__ void prep_fc(const float* __restrict__ fco_w) {
    const int total = 9 * H_ * 32;
    for (int idx = blockIdx.x * blockDim.x + threadIdx.x; idx < total;
         idx += gridDim.x * blockDim.x) {
        int cc = idx & 31;
        int k = (idx >> 5) & (H_ - 1);
        int ct = idx >> 15;
        int c = ct * 32 + cc;
        g_FCpk[idx] = (c < C_) ? fco_w[(size_t)c * H_ + k] : 0.0f;
    }
}

__global__ void prep_xt(const float* __restrict__ x) {
    const int total = T_ * F_ * B_;
    for (int idx = blockIdx.x * blockDim.x + threadIdx.x; idx < total;
         idx += gridDim.x * blockDim.x) {
        int b = idx & (B_ - 1);
        int k = (idx >> 6) & (F_ - 1);
        int t = idx >> 14;
        g_xT[idx] = x[((size_t)t * B_ + b) * F_ + k];
    }
}

__global__ void prep_zero() {
    int i = blockIdx.x * blockDim.x + threadIdx.x;
    if (i < T_ * 128) g_flag[i] = 0;
}

// ---------------------------------------------------------------------------
// GEMM core for gates/out kernels (known-good from R1).
// ---------------------------------------------------------------------------
template <int NK>
__device__ __forceinline__ void gemm_core(const float4* __restrict__ Ag,
                                          const float4* __restrict__ Bg,
                                          float4 (*sA)[256], float4 (*sB)[512],
                                          ull (&acc)[4][2]) {
    const int tid = threadIdx.x;
    const int tn = tid >> 4;
    const int tb = tid & 15;

    float4 ra0, ra1, rb0, rb1, rb2, rb3;
    ra0 = Ag[tid];       ra1 = Ag[tid + 128];
    rb0 = Bg[tid];       rb1 = Bg[tid + 128];
    rb2 = Bg[tid + 256]; rb3 = Bg[tid + 384];
    sA[0][tid] = ra0;       sA[0][tid + 128] = ra1;
    sB[0][tid] = rb0;       sB[0][tid + 128] = rb1;
    sB[0][tid + 256] = rb2; sB[0][tid + 384] = rb3;
    __syncthreads();

#pragma unroll 1
    for (int ch = 0; ch < NK; ++ch) {
        const int cur = ch & 1;
        const int nxt = cur ^ 1;
        if (ch + 1 < NK) {
            const float4* An = Ag + (size_t)(ch + 1) * 256;
            const float4* Bn = Bg + (size_t)(ch + 1) * 512;
            ra0 = An[tid];       ra1 = An[tid + 128];
            rb0 = Bn[tid];       rb1 = Bn[tid + 128];
            rb2 = Bn[tid + 256]; rb3 = Bn[tid + 384];
        }
        const float4* A = sA[cur];
        const float4* Bv = sB[cur];
#pragma unroll
        for (int kk = 0; kk < 32; ++kk) {
            float4 a = A[kk * 8 + tn];
            const ull* bp = reinterpret_cast<const ull*>(&Bv[kk * 16 + tb]);
            ull b0 = bp[0];
            ull b1 = bp[1];
            ull a0 = pkdup(a.x);
            ull a1 = pkdup(a.y);
            ull a2 = pkdup(a.z);
            ull a3 = pkdup(a.w);
            fma2(acc[0][0], a0, b0); fma2(acc[0][1], a0, b1);
            fma2(acc[1][0], a1, b0); fma2(acc[1][1], a1, b1);
            fma2(acc[2][0], a2, b0); fma2(acc[2][1], a2, b1);
            fma2(acc[3][0], a3, b0); fma2(acc[3][1], a3, b1);
        }
        __syncthreads();
        if (ch + 1 < NK) {
            sA[nxt][tid] = ra0;       sA[nxt][tid + 128] = ra1;
            sB[nxt][tid] = rb0;       sB[nxt][tid + 128] = rb1;
            sB[nxt][tid + 256] = rb2; sB[nxt][tid + 384] = rb3;
            __syncthreads();
        }
    }
}

__device__ __forceinline__ void unpack_acc(const ull (&acc)[4][2], float (&z)[4][4]) {
#pragma unroll
    for (int r = 0; r < 4; ++r) {
        z[r][0] = lo2(acc[r][0]);
        z[r][1] = hi2(acc[r][0]);
        z[r][2] = lo2(acc[r][1]);
        z[r][3] = hi2(acc[r][1]);
    }
}

// ---------------------------------------------------------------------------
// Input-projection GEMM: gates[t][j][b][4]
// ---------------------------------------------------------------------------
__global__ void k_gates(const float* __restrict__ bf, const float* __restrict__ bi,
                        const float* __restrict__ bo, const float* __restrict__ bc) {
    const int jt = blockIdx.x;
    const int t = blockIdx.y;
    __shared__ float4 sA[2][256];
    __shared__ float4 sB[2][512];
    ull acc[4][2] = {};

    const float4* Ag = reinterpret_cast<const float4*>(g_WXpk) + (size_t)jt * F_ * 8;
    const float4* Bg = reinterpret_cast<const float4*>(g_xT) + (size_t)t * F_ * 16;
    gemm_core<F_ / 32>(Ag, Bg, sA, sB, acc);

    const int tn = threadIdx.x >> 4;
    const int tb = threadIdx.x & 15;
    const int j = jt * 8 + tn;
    float z[4][4];
    unpack_acc(acc, z);
    const float b0 = bf[j], b1 = bi[j], b2 = bo[j], b3 = bc[j];
    float4* G = reinterpret_cast<float4*>(g_gates) + ((size_t)t * H_ + j) * 64 + tb * 4;
#pragma unroll
    for (int bb = 0; bb < 4; ++bb) {
        G[bb] = make_float4(z[0][bb] + b0, z[1][bb] + b1, z[2][bb] + b2, z[3][bb] + b3);
    }
}

// ---------------------------------------------------------------------------
// Persistent recurrence kernel. 128 CTAs x 256 threads. CTA jt owns rows
// j = jt*8..+7 (32 gate-rows). Weights resident in SMEM (128 KB) all 512 steps.
// B (h of t-1) staged per 64-k chunk, single-sync double buffer, kk-pair
// interleaved so one LDS.128 feeds 2 k-steps of the B operand.
// Release protocol (R2-proven): per-thread __threadfence -> bar -> tid0 flag.
// ---------------------------------------------------------------------------
__global__ void __launch_bounds__(256, 1) k_rec() {
    extern __shared__ float smem[];
    float* sW = smem;              // [1024][32]  = 128 KB
    float* sB2 = smem + H_ * 32;   // 2 x [32 kk2][64 b][2] = 2 x 16 KB

    const int tid = threadIdx.x;
    const int jt = blockIdx.x;

    // Load this CTA's weight slice once (128 KB).
    {
        const float4* Wg =
            reinterpret_cast<const float4*>(g_Wpk + (size_t)jt * H_ * 32);
        float4* sW4 = reinterpret_cast<float4*>(sW);
#pragma unroll
        for (int i = 0; i < 32; ++i) sW4[tid + i * 256] = Wg[tid + i * 256];
    }
    __syncthreads();

    const int wid = tid >> 5, lane = tid & 31;
    const int wr = wid >> 2, wc = wid & 3;
    const int lr = lane >> 3, cb = lane & 7;
    const int rr = wr * 16 + lr * 4;  // row base within 32-row tile (= jj*4)
    const int j = jt * 8 + (rr >> 2);
    const int b0 = wc * 16 + cb * 2;

    float c0 = 0.f, c1 = 0.f;
    float4* sB4 = reinterpret_cast<float4*>(sB2);

#pragma unroll 1
    for (int t = 0; t < T_; ++t) {
        // Prefetch this step's input-projection gates (independent of flags).
        const float4* G4 =
            reinterpret_cast<const float4*>(g_gates) + ((size_t)t * H_ + j) * 64 + b0;
        float4 gx0 = G4[0];
        float4 gx1 = G4[1];

        ull acc00 = 0, acc01 = 0, acc10 = 0, acc11 = 0;
        if (t > 0) {
            // One parallel wait for all 128 producer flags of step t-1.
            if (tid < 128) {
                const int* f = g_flag + (t - 1) * 128 + tid;
                int v;
                do {
                    asm volatile("ld.volatile.global.s32 %0, [%1];"
                                 : "=r"(v) : "l"(f));
                } while (!v);
            }
            __syncthreads();

            const float4* hp4 =
                reinterpret_cast<const float4*>(g_hT2) + (size_t)(t - 1) * 16384;

            // Stage chunk 0 (16 KB -> buffer 0).
            {
                float4 p0 = hp4[tid], p1 = hp4[tid + 256];
                float4 p2 = hp4[tid + 512], p3 = hp4[tid + 768];
                sB4[tid] = p0;        sB4[tid + 256] = p1;
                sB4[tid + 512] = p2;  sB4[tid + 768] = p3;
            }
            __syncthreads();

#pragma unroll 1
            for (int kc = 0; kc < 16; ++kc) {
                float4 q0, q1, q2, q3;
                if (kc < 15) {
                    const float4* hn = hp4 + (size_t)(kc + 1) * 1024;
                    q0 = hn[tid];       q1 = hn[tid + 256];
                    q2 = hn[tid + 512]; q3 = hn[tid + 768];
                }
                const float* Wk = sW + (kc * 64) * 32;
                const float* Bc = sB2 + (kc & 1) * 4096;
#pragma unroll
                for (int kk2 = 0; kk2 < 32; ++kk2) {
                    ulonglong2 av0 =
                        *reinterpret_cast<const ulonglong2*>(Wk + (2 * kk2) * 32 + rr);
                    ulonglong2 av1 =
                        *reinterpret_cast<const ulonglong2*>(Wk + (2 * kk2 + 1) * 32 + rr);
                    float4 bq =
                        *reinterpret_cast<const float4*>(Bc + kk2 * 128 + b0 * 2);
                    ull b00 = pkdup(bq.x);  // kk even, col b0
                    ull b10 = pkdup(bq.y);  // kk odd,  col b0
                    ull b01 = pkdup(bq.z);  // kk even, col b0+1
                    ull b11 = pkdup(bq.w);  // kk odd,  col b0+1
                    fma2(acc00, av0.x, b00); fma2(acc10, av0.y, b00);
                    fma2(acc01, av0.x, b01); fma2(acc11, av0.y, b01);
                    fma2(acc00, av1.x, b10); fma2(acc10, av1.y, b10);
                    fma2(acc01, av1.x, b11); fma2(acc11, av1.y, b11);
                }
                if (kc < 15) {
                    float4* nb = reinterpret_cast<float4*>(sB2 + ((kc + 1) & 1) * 4096);
                    nb[tid] = q0;       nb[tid + 256] = q1;
                    nb[tid + 512] = q2; nb[tid + 768] = q3;
                    __syncthreads();
                }
            }
        }

        // Epilogue: add input gates, LSTM cell, write h (both layouts), flag.
        float zf0 = lo2(acc00) + gx0.x, zi0 = hi2(acc00) + gx0.y;
        float zo0 = lo2(acc10) + gx0.z, zc0 = hi2(acc10) + gx0.w;
        float zf1 = lo2(acc01) + gx1.x, zi1 = hi2(acc01) + gx1.y;
        float zo1 = lo2(acc11) + gx1.z, zc1 = hi2(acc11) + gx1.w;

        float ft0 = sigf(zf0), it0 = sigf(zi0), ot0 = sigf(zo0);
        c0 = it0 * tanh_acc(zc0) + ft0 * c0;
        float h0v = ot0 * tanh_acc(c0);
        float ft1 = sigf(zf1), it1 = sigf(zi1), ot1 = sigf(zo1);
        c1 = it1 * tanh_acc(zc1) + ft1 * c1;
        float h1v = ot1 * tanh_acc(c1);

        // Plain layout for k_out.
        *reinterpret_cast<float2*>(g_hT + (size_t)t * (H_ * B_) + j * B_ + b0) =
            make_float2(h0v, h1v);
        // kk-pair interleaved layout for k_rec's B loads.
        {
            float* p = g_hT2 + (((size_t)t * 512 + (j >> 1)) * 64 + b0) * 2 + (j & 1);
            p[0] = h0v;
            p[2] = h1v;
        }
        // R2-proven release: every thread fences its own stores, then bar,
        // then one thread publishes the flag.
        __threadfence();
        __syncthreads();
        if (tid == 0) {
            asm volatile("st.volatile.global.s32 [%0], %1;"
                         :: "l"(g_flag + t * 128 + jt), "r"(1)
                         : "memory");
        }
    }
}

// ---------------------------------------------------------------------------
// Output projection: out[t][b][c] = hT[t][:,b] . fco_w[c,:] + fco_b[c]
// ---------------------------------------------------------------------------
__global__ void k_out(const float* __restrict__ fco_b, float* __restrict__ out) {
    const int ct = blockIdx.x;
    const int t = blockIdx.y;
    __shared__ float4 sA[2][256];
    __shared__ float4 sB[2][512];
    ull acc[4][2] = {};

    const float4* Ag = reinterpret_cast<const float4*>(g_FCpk) + (size_t)ct * H_ * 8;
    const float4* Bg = reinterpret_cast<const float4*>(g_hT) + (size_t)t * H_ * 16;
    gemm_core<H_ / 32>(Ag, Bg, sA, sB, acc);

    const int tn = threadIdx.x >> 4;
    const int tb = threadIdx.x & 15;
    const int c0 = ct * 32 + tn * 4;

    float z[4][4];
    unpack_acc(acc, z);

#pragma unroll
    for (int bb = 0; bb < 4; ++bb) {
        const int b = tb * 4 + bb;
        float* o = out + ((size_t)t * B_ + b) * C_;
#pragma unroll
        for (int ci = 0; ci < 4; ++ci) {
            const int c = c0 + ci;
            if (c < C_) o[c] = z[ci][bb] + fco_b[c];
        }
    }
}

// ---------------------------------------------------------------------------
// Launch
// ---------------------------------------------------------------------------
extern "C" void kernel_launch(void* const* d_in, const int* in_sizes, int n_in,
                              void* d_out, int out_size) {
    const float* x     = (const float*)d_in[0];
    const float* wfx_w = (const float*)d_in[1];
    const float* wfx_b = (const float*)d_in[2];
    const float* wix_w = (const float*)d_in[3];
    const float* wix_b = (const float*)d_in[4];
    const float* wox_w = (const float*)d_in[5];
    const float* wox_b = (const float*)d_in[6];
    const float* wcx_w = (const float*)d_in[7];
    const float* wcx_b = (const float*)d_in[8];
    const float* wfh_w = (const float*)d_in[9];
    const float* wih_w = (const float*)d_in[10];
    const float* woh_w = (const float*)d_in[11];
    const float* wch_w = (const float*)d_in[12];
    const float* fco_w = (const float*)d_in[13];
    const float* fco_b = (const float*)d_in[14];
    float* out = (float*)d_out;

    (void)in_sizes; (void)n_in; (void)out_size;

    const int rec_smem = (H_ * 32 + 2 * 4096) * (int)sizeof(float); // 163840
    cudaFuncSetAttribute(k_rec, cudaFuncAttributeMaxDynamicSharedMemorySize,
                         rec_smem);

    prep_wh<<<4096, 256>>>(wfh_w, wih_w, woh_w, wch_w);
    prep_wx<<<2048, 256>>>(wfx_w, wix_w, wox_w, wcx_w);
    prep_fc<<<576, 256>>>(fco_w);
    prep_xt<<<4096, 256>>>(x);
    prep_zero<<<256, 256>>>();

    k_gates<<<dim3(128, 512), 128>>>(wfx_b, wix_b, wox_b, wcx_b);

    k_rec<<<128, 256, rec_smem>>>();

    k_out<<<dim3(9, 512), 128>>>(fco_b, out);
}

// round 10
// speedup vs baseline: 2.3444x; 1.6915x over previous
#include <cuda_runtime.h>
#include <cuda_bf16.h>
#include <math.h>
#include <stdint.h>

typedef unsigned long long ull;

#define T_ 512
#define B_ 64
#define F_ 256
#define H_ 1024
#define C_ 257

// ---------------- scratch ----------------
__device__ float g_gates[(size_t)T_ * H_ * B_ * 4]; // [t][j][b][g]
__device__ float g_hT[(size_t)T_ * H_ * B_];        // [t][j][b] (k_out)
__device__ float g_WXpk[(size_t)128 * F_ * 32];
__device__ float g_FCpk[(size_t)9 * H_ * 32];
__device__ float g_xT[(size_t)T_ * F_ * B_];
// W in mma A-fragment order: [cta128][w8][mt2][kt8][split2][reg4][lane32] u32
__device__ uint32_t g_Wfrag[(size_t)128 * 8 * 2 * 8 * 2 * 4 * 32];
// h in mma B-fragment order: [parity2][w8][kt8][nt8][split2][lane32][rb2] u32
__device__ uint32_t g_hfrag[(size_t)2 * 65536];
__device__ int g_flag[(size_t)T_ * 128];

// ---------------- helpers ----------------
__device__ __forceinline__ ull pkdup(float v) {
    ull r; asm("mov.b64 %0, {%1, %1};" : "=l"(r) : "r"(__float_as_uint(v))); return r;
}
__device__ __forceinline__ void fma2(ull& d, ull a, ull b) {
    asm("fma.rn.f32x2 %0, %1, %2, %0;" : "+l"(d) : "l"(a), "l"(b));
}
__device__ __forceinline__ float lo2(ull v) { return __uint_as_float((unsigned)v); }
__device__ __forceinline__ float hi2(ull v) { return __uint_as_float((unsigned)(v >> 32)); }
__device__ __forceinline__ float sigf(float x) { return 1.0f / (1.0f + expf(-x)); }
__device__ __forceinline__ float tanh_acc(float x) {
    float ax = fabsf(x), e = expf(-2.0f * ax);
    return copysignf((1.0f - e) / (1.0f + e), x);
}
__device__ __forceinline__ uint2 ldg_cg2(const uint32_t* p) {
    uint2 v;
    asm volatile("ld.global.cg.v2.u32 {%0,%1}, [%2];" : "=r"(v.x), "=r"(v.y) : "l"(p));
    return v;
}
__device__ __forceinline__ void mma_bf16(float& d0, float& d1, float& d2, float& d3,
                                         uint32_t a0, uint32_t a1, uint32_t a2,
                                         uint32_t a3, uint32_t b0, uint32_t b1) {
    asm volatile(
        "mma.sync.aligned.m16n8k16.row.col.f32.bf16.bf16.f32 "
        "{%0,%1,%2,%3},{%4,%5,%6,%7},{%8,%9},{%0,%1,%2,%3};"
        : "+f"(d0), "+f"(d1), "+f"(d2), "+f"(d3)
        : "r"(a0), "r"(a1), "r"(a2), "r"(a3), "r"(b0), "r"(b1));
}
__device__ __forceinline__ uint32_t bfbits(float v) {
    return (uint32_t)__bfloat16_as_ushort(__float2bfloat16(v));
}

// ---------------- prep kernels ----------------
// A-fragment pack. r = mt*16 + (lane>>2) + (reg&1)*8 (CTA row, = g*8+jj);
// k = w*128 + kt*16 + (lane&3)*2 + (reg>>1)*8.
__global__ void prep_wfrag(const float* __restrict__ wf, const float* __restrict__ wi,
                           const float* __restrict__ wo, const float* __restrict__ wc) {
    const int total = 128 << 15;
    for (int idx = blockIdx.x * blockDim.x + threadIdx.x; idx < total;
         idx += gridDim.x * blockDim.x) {
        int lane = idx & 31, reg = (idx >> 5) & 3, split = (idx >> 7) & 1;
        int kt = (idx >> 8) & 7, mt = (idx >> 11) & 1, w = (idx >> 12) & 7;
        int cta = idx >> 15;
        int r = mt * 16 + (lane >> 2) + (reg & 1) * 8;
        int k = w * 128 + kt * 16 + (lane & 3) * 2 + (reg >> 1) * 8;
        int g = r >> 3, jj = r & 7, j = cta * 8 + jj;
        const float* W = (g == 0) ? wf : (g == 1) ? wi : (g == 2) ? wo : wc;
        float v0 = W[(size_t)j * H_ + k], v1 = W[(size_t)j * H_ + k + 1];
        uint32_t word;
        if (split == 0) {
            word = bfbits(v0) | (bfbits(v1) << 16);
        } else {
            float h0 = __bfloat162float(__float2bfloat16(v0));
            float h1 = __bfloat162float(__float2bfloat16(v1));
            word = bfbits(v0 - h0) | (bfbits(v1 - h1) << 16);
        }
        g_Wfrag[idx] = word;
    }
}
__global__ void prep_wx(const float* __restrict__ wf, const float* __restrict__ wi,
                        const float* __restrict__ wo, const float* __restrict__ wc) {
    const int total = 128 * F_ * 32;
    for (int idx = blockIdx.x * blockDim.x + threadIdx.x; idx < total;
         idx += gridDim.x * blockDim.x) {
        int r = idx & 31, k = (idx >> 5) & (F_ - 1), jt = idx >> 13;
        int g = r & 3, jj = r >> 2, j = jt * 8 + jj;
        const float* w = (g == 0) ? wf : (g == 1) ? wi : (g == 2) ? wo : wc;
        g_WXpk[idx] = w[(size_t)j * F_ + k];
    }
}
__global__ void prep_fc(const float* __restrict__ fco_w) {
    const int total = 9 * H_ * 32;
    for (int idx = blockIdx.x * blockDim.x + threadIdx.x; idx < total;
         idx += gridDim.x * blockDim.x) {
        int cc = idx & 31, k = (idx >> 5) & (H_ - 1), ct = idx >> 15;
        int c = ct * 32 + cc;
        g_FCpk[idx] = (c < C_) ? fco_w[(size_t)c * H_ + k] : 0.0f;
    }
}
__global__ void prep_xt(const float* __restrict__ x) {
    const int total = T_ * F_ * B_;
    for (int idx = blockIdx.x * blockDim.x + threadIdx.x; idx < total;
         idx += gridDim.x * blockDim.x) {
        int b = idx & (B_ - 1), k = (idx >> 6) & (F_ - 1), t = idx >> 14;
        g_xT[idx] = x[((size_t)t * B_ + b) * F_ + k];
    }
}
__global__ void prep_zero() {
    int i = blockIdx.x * blockDim.x + threadIdx.x;
    if (i < T_ * 128) g_flag[i] = 0;
}

// ---------------- SIMT GEMM core (known-good) ----------------
template <int NK>
__device__ __forceinline__ void gemm_core(const float4* __restrict__ Ag,
                                          const float4* __restrict__ Bg,
                                          float4 (*sA)[256], float4 (*sB)[512],
                                          ull (&acc)[4][2]) {
    const int tid = threadIdx.x, tn = tid >> 4, tb = tid & 15;
    float4 ra0, ra1, rb0, rb1, rb2, rb3;
    ra0 = Ag[tid]; ra1 = Ag[tid + 128];
    rb0 = Bg[tid]; rb1 = Bg[tid + 128]; rb2 = Bg[tid + 256]; rb3 = Bg[tid + 384];
    sA[0][tid] = ra0; sA[0][tid + 128] = ra1;
    sB[0][tid] = rb0; sB[0][tid + 128] = rb1;
    sB[0][tid + 256] = rb2; sB[0][tid + 384] = rb3;
    __syncthreads();
#pragma unroll 1
    for (int ch = 0; ch < NK; ++ch) {
        const int cur = ch & 1, nxt = cur ^ 1;
        if (ch + 1 < NK) {
            const float4* An = Ag + (size_t)(ch + 1) * 256;
            const float4* Bn = Bg + (size_t)(ch + 1) * 512;
            ra0 = An[tid]; ra1 = An[tid + 128];
            rb0 = Bn[tid]; rb1 = Bn[tid + 128];
            rb2 = Bn[tid + 256]; rb3 = Bn[tid + 384];
        }
        const float4* A = sA[cur];
        const float4* Bv = sB[cur];
#pragma unroll
        for (int kk = 0; kk < 32; ++kk) {
            float4 a = A[kk * 8 + tn];
            const ull* bp = reinterpret_cast<const ull*>(&Bv[kk * 16 + tb]);
            ull b0 = bp[0], b1 = bp[1];
            ull a0 = pkdup(a.x), a1 = pkdup(a.y), a2 = pkdup(a.z), a3 = pkdup(a.w);
            fma2(acc[0][0], a0, b0); fma2(acc[0][1], a0, b1);
            fma2(acc[1][0], a1, b0); fma2(acc[1][1], a1, b1);
            fma2(acc[2][0], a2, b0); fma2(acc[2][1], a2, b1);
            fma2(acc[3][0], a3, b0); fma2(acc[3][1], a3, b1);
        }
        __syncthreads();
        if (ch + 1 < NK) {
            sA[nxt][tid] = ra0; sA[nxt][tid + 128] = ra1;
            sB[nxt][tid] = rb0; sB[nxt][tid + 128] = rb1;
            sB[nxt][tid + 256] = rb2; sB[nxt][tid + 384] = rb3;
            __syncthreads();
        }
    }
}
__device__ __forceinline__ void unpack_acc(const ull (&acc)[4][2], float (&z)[4][4]) {
#pragma unroll
    for (int r = 0; r < 4; ++r) {
        z[r][0] = lo2(acc[r][0]); z[r][1] = hi2(acc[r][0]);
        z[r][2] = lo2(acc[r][1]); z[r][3] = hi2(acc[r][1]);
    }
}

__global__ void k_gates(const float* __restrict__ bf, const float* __restrict__ bi,
                        const float* __restrict__ bo, const float* __restrict__ bc) {
    const int jt = blockIdx.x, t = blockIdx.y;
    __shared__ float4 sA[2][256];
    __shared__ float4 sB[2][512];
    ull acc[4][2] = {};
    const float4* Ag = reinterpret_cast<const float4*>(g_WXpk) + (size_t)jt * F_ * 8;
    const float4* Bg = reinterpret_cast<const float4*>(g_xT) + (size_t)t * F_ * 16;
    gemm_core<F_ / 32>(Ag, Bg, sA, sB, acc);
    const int tn = threadIdx.x >> 4, tb = threadIdx.x & 15, j = jt * 8 + tn;
    float z[4][4];
    unpack_acc(acc, z);
    const float b0 = bf[j], b1 = bi[j], b2 = bo[j], b3 = bc[j];
    float4* G = reinterpret_cast<float4*>(g_gates) + ((size_t)t * H_ + j) * 64 + tb * 4;
#pragma unroll
    for (int bb = 0; bb < 4; ++bb)
        G[bb] = make_float4(z[0][bb] + b0, z[1][bb] + b1, z[2][bb] + b2, z[3][bb] + b3);
}

// ---------------- persistent mma.sync recurrence ----------------
// 128 CTAs x 256 thr (8 warps). CTA owns j = cta*8..+7 (32 gate-rows:
// r = g*8+jj). Warp w owns K-slice w*128..+127; A frags register-resident.
#define SM_PART 0        // 64 KB: [w][mt][nt][lane][reg] f32
#define SM_ZBUF 65536    // 32 x 66 f32
#define REC_SMEM (65536 + 32 * 66 * 4)

__global__ void __launch_bounds__(256, 1) k_rec3() {
    extern __shared__ unsigned char sm[];
    float* part = reinterpret_cast<float*>(sm + SM_PART);
    float* zbuf = reinterpret_cast<float*>(sm + SM_ZBUF);

    const int tid = threadIdx.x, w = tid >> 5, lane = tid & 31;
    const int cta = blockIdx.x;

    // Load A fragments (held in registers for all 512 steps).
    uint32_t A[2][8][2][4];  // [mt][kt][split][reg]
    {
        const uint32_t* src = g_Wfrag + ((size_t)cta * 8 + w) * 4096 + lane;
#pragma unroll
        for (int mt = 0; mt < 2; ++mt)
#pragma unroll
            for (int kt = 0; kt < 8; ++kt)
#pragma unroll
                for (int sp = 0; sp < 2; ++sp)
#pragma unroll
                    for (int rg = 0; rg < 4; ++rg)
                        A[mt][kt][sp][rg] =
                            src[((((mt * 8 + kt) * 2 + sp) * 4 + rg) << 5)];
    }

    const int jj = tid >> 5;            // epilogue row (0..7)
    const int b0 = (tid & 31) * 2;      // epilogue batch pair
    const int j = cta * 8 + jj;
    float cst0 = 0.f, cst1 = 0.f;
    // h-frag write coords for (j, b): w_j, kt_j fixed per thread.
    const int w_j = j >> 7, kt_j = (j >> 4) & 7, rb_j = (j >> 3) & 1;
    const int byte_in = (j & 1) * 2;
    const int l_j0 = ((b0 & 7) << 2) + ((j & 7) >> 1);        // lane for b0
    const int l_j1 = (((b0 + 1) & 7) << 2) + ((j & 7) >> 1);  // lane for b0+1

#pragma unroll 1
    for (int t = 0; t < T_; ++t) {
        float zadd[4][2];  // [gate][b-pair] recurrent contribution
        if (t > 0) {
            if (tid < 128) {
                const int* f = g_flag + (t - 1) * 128 + tid;
                int v;
                do {
                    asm volatile("ld.volatile.global.s32 %0, [%1];" : "=r"(v) : "l"(f));
                } while (!v);
            }
            __syncthreads();

            float D[2][8][4];
#pragma unroll
            for (int mt = 0; mt < 2; ++mt)
#pragma unroll
                for (int nt = 0; nt < 8; ++nt)
#pragma unroll
                    for (int rg = 0; rg < 4; ++rg) D[mt][nt][rg] = 0.f;

            const uint32_t* himg = g_hfrag + (size_t)((t - 1) & 1) * 65536;
#pragma unroll
            for (int kt = 0; kt < 8; ++kt) {
#pragma unroll
                for (int nt = 0; nt < 8; ++nt) {
                    const uint32_t* bb =
                        himg + (((w * 8 + kt) * 8 + nt) * 2) * 64 + lane * 2;
                    uint2 bh = ldg_cg2(bb);
                    uint2 bl = ldg_cg2(bb + 64);
#pragma unroll
                    for (int mt = 0; mt < 2; ++mt) {
                        mma_bf16(D[mt][nt][0], D[mt][nt][1], D[mt][nt][2], D[mt][nt][3],
                                 A[mt][kt][0][0], A[mt][kt][0][1], A[mt][kt][0][2],
                                 A[mt][kt][0][3], bh.x, bh.y);
                        mma_bf16(D[mt][nt][0], D[mt][nt][1], D[mt][nt][2], D[mt][nt][3],
                                 A[mt][kt][0][0], A[mt][kt][0][1], A[mt][kt][0][2],
                                 A[mt][kt][0][3], bl.x, bl.y);
                        mma_bf16(D[mt][nt][0], D[mt][nt][1], D[mt][nt][2], D[mt][nt][3],
                                 A[mt][kt][1][0], A[mt][kt][1][1], A[mt][kt][1][2],
                                 A[mt][kt][1][3], bh.x, bh.y);
                    }
                }
            }
            // Store K-partials.
#pragma unroll
            for (int mt = 0; mt < 2; ++mt)
#pragma unroll
                for (int nt = 0; nt < 8; ++nt)
                    *reinterpret_cast<float4*>(
                        part + ((((w * 2 + mt) * 8 + nt) * 32) + lane) * 4) =
                        make_float4(D[mt][nt][0], D[mt][nt][1], D[mt][nt][2],
                                    D[mt][nt][3]);
            __syncthreads();
            // Reduce over 8 warps -> zbuf[r][n].
#pragma unroll
            for (int cc = 0; cc < 2; ++cc) {
                int c = tid + cc * 256;
                int mt = c >> 8, nt = (c >> 5) & 7, ln = c & 31;
                float4 s = make_float4(0.f, 0.f, 0.f, 0.f);
#pragma unroll
                for (int ww = 0; ww < 8; ++ww) {
                    float4 p = *reinterpret_cast<const float4*>(
                        part + ((((ww * 2 + mt) * 8 + nt) * 32) + ln) * 4);
                    s.x += p.x; s.y += p.y; s.z += p.z; s.w += p.w;
                }
                int r = mt * 16 + (ln >> 2);
                int n = nt * 8 + (ln & 3) * 2;
                *reinterpret_cast<float2*>(zbuf + r * 66 + n) = make_float2(s.x, s.y);
                *reinterpret_cast<float2*>(zbuf + (r + 8) * 66 + n) =
                    make_float2(s.z, s.w);
            }
            __syncthreads();
#pragma unroll
            for (int g = 0; g < 4; ++g) {
                float2 v = *reinterpret_cast<const float2*>(zbuf + (g * 8 + jj) * 66 + b0);
                zadd[g][0] = v.x;
                zadd[g][1] = v.y;
            }
            __syncthreads();  // zbuf/part free before next step
        } else {
#pragma unroll
            for (int g = 0; g < 4; ++g) zadd[g][0] = zadd[g][1] = 0.f;
        }

        // LSTM cell: 2 cells (j, b0) and (j, b0+1).
        const float4* G4 = reinterpret_cast<const float4*>(g_gates) +
                           ((size_t)t * H_ + j) * 64 + b0;
        float4 gx0 = G4[0], gx1 = G4[1];
        float ft0 = sigf(gx0.x + zadd[0][0]), it0 = sigf(gx0.y + zadd[1][0]);
        float ot0 = sigf(gx0.z + zadd[2][0]);
        cst0 = it0 * tanh_acc(gx0.w + zadd[3][0]) + ft0 * cst0;
        float h0 = ot0 * tanh_acc(cst0);
        float ft1 = sigf(gx1.x + zadd[0][1]), it1 = sigf(gx1.y + zadd[1][1]);
        float ot1 = sigf(gx1.z + zadd[2][1]);
        cst1 = it1 * tanh_acc(gx1.w + zadd[3][1]) + ft1 * cst1;
        float h1 = ot1 * tanh_acc(cst1);

        // fp32 h for k_out.
        *reinterpret_cast<float2*>(g_hT + ((size_t)t * H_ + j) * B_ + b0) =
            make_float2(h0, h1);
        // bf16 hi/lo B-fragment image (parity t&1).
        {
            uint32_t* img = g_hfrag + (size_t)(t & 1) * 65536;
            const int nt = b0 >> 3;  // b0, b0+1 share nt (b0 even)
            size_t base = (((w_j * 8 + kt_j) * 8 + nt) * 2) * 64;
            unsigned char* pH0 = (unsigned char*)(img + base + l_j0 * 2 + rb_j) + byte_in;
            unsigned char* pH1 = (unsigned char*)(img + base + l_j1 * 2 + rb_j) + byte_in;
            unsigned char* pL0 = pH0 + 64 * 4;
            unsigned char* pL1 = pH1 + 64 * 4;
            __nv_bfloat16 h0h = __float2bfloat16(h0);
            __nv_bfloat16 h1h = __float2bfloat16(h1);
            *(__nv_bfloat16*)pH0 = h0h;
            *(__nv_bfloat16*)pH1 = h1h;
            *(__nv_bfloat16*)pL0 = __float2bfloat16(h0 - __bfloat162float(h0h));
            *(__nv_bfloat16*)pL1 = __float2bfloat16(h1 - __bfloat162float(h1h));
        }
        __threadfence();
        __syncthreads();
        if (tid == 0) {
            asm volatile("st.volatile.global.s32 [%0], %1;"
                         :: "l"(g_flag + t * 128 + cta), "r"(1) : "memory");
        }
    }
}

// ---------------- output projection ----------------
__global__ void k_out(const float* __restrict__ fco_b, float* __restrict__ out) {
    const int ct = blockIdx.x, t = blockIdx.y;
    __shared__ float4 sA[2][256];
    __shared__ float4 sB[2][512];
    ull acc[4][2] = {};
    const float4* Ag = reinterpret_cast<const float4*>(g_FCpk) + (size_t)ct * H_ * 8;
    const float4* Bg = reinterpret_cast<const float4*>(g_hT) + (size_t)t * H_ * 16;
    gemm_core<H_ / 32>(Ag, Bg, sA, sB, acc);
    const int tn = threadIdx.x >> 4, tb = threadIdx.x & 15, c0 = ct * 32 + tn * 4;
    float z[4][4];
    unpack_acc(acc, z);
#pragma unroll
    for (int bb = 0; bb < 4; ++bb) {
        const int b = tb * 4 + bb;
        float* o = out + ((size_t)t * B_ + b) * C_;
#pragma unroll
        for (int ci = 0; ci < 4; ++ci) {
            const int c = c0 + ci;
            if (c < C_) o[c] = z[ci][bb] + fco_b[c];
        }
    }
}

// ---------------- launch ----------------
extern "C" void kernel_launch(void* const* d_in, const int* in_sizes, int n_in,
                              void* d_out, int out_size) {
    const float* x     = (const float*)d_in[0];
    const float* wfx_w = (const float*)d_in[1];
    const float* wfx_b = (const float*)d_in[2];
    const float* wix_w = (const float*)d_in[3];
    const float* wix_b = (const float*)d_in[4];
    const float* wox_w = (const float*)d_in[5];
    const float* wox_b = (const float*)d_in[6];
    const float* wcx_w = (const float*)d_in[7];
    const float* wcx_b = (const float*)d_in[8];
    const float* wfh_w = (const float*)d_in[9];
    const float* wih_w = (const float*)d_in[10];
    const float* woh_w = (const float*)d_in[11];
    const float* wch_w = (const float*)d_in[12];
    const float* fco_w = (const float*)d_in[13];
    const float* fco_b = (const float*)d_in[14];
    float* out = (float*)d_out;
    (void)in_sizes; (void)n_in; (void)out_size;

    cudaFuncSetAttribute(k_rec3, cudaFuncAttributeMaxDynamicSharedMemorySize,
                         REC_SMEM);

    prep_wfrag<<<8192, 256>>>(wfh_w, wih_w, woh_w, wch_w);
    prep_wx<<<2048, 256>>>(wfx_w, wix_w, wox_w, wcx_w);
    prep_fc<<<576, 256>>>(fco_w);
    prep_xt<<<4096, 256>>>(x);
    prep_zero<<<256, 256>>>();

    k_gates<<<dim3(128, 512), 128>>>(wfx_b, wix_b, wox_b, wcx_b);

    k_rec3<<<128, 256, REC_SMEM>>>();

    k_out<<<dim3(9, 512), 128>>>(fco_b, out);
}